// round 17
// baseline (speedup 1.0000x reference)
#include <cuda_runtime.h>
#include <cuda_bf16.h>
#include <cstdint>
#include <cstddef>

#define BATCH 8
#define CC    512
#define LL    2048
#define NGROUPS 32
#define CPG   (CC / NGROUPS)
#define GROUP_ELEMS (CPG * LL)
#define EPS   1e-5f

// ---------------------------------------------------------------------------
// Device scratch (all GEMM operands k-contiguous)
// ---------------------------------------------------------------------------
__device__ __nv_bfloat16 g_hT[(size_t)BATCH * LL * CC];   // [b][l][c]
__device__ __nv_bfloat16 g_qT[(size_t)BATCH * LL * CC];   // [b][l][c]
__device__ __nv_bfloat16 g_kT[(size_t)BATCH * LL * CC];   // [b][l][c]
__device__ __nv_bfloat16 g_v [(size_t)BATCH * CC * LL];   // [b][c][l]  (= Wov@h)
__device__ __nv_bfloat16 g_e [(size_t)BATCH * LL * LL];   // exp(scores) bf16
__device__ float         g_part[(size_t)BATCH * LL * 32]; // rowsum partials
__device__ float         g_invrs[(size_t)BATCH * LL];     // 1/rowsum
__device__ float2        g_stats[BATCH * NGROUPS];
__device__ __nv_bfloat16 g_Wbf[4 * CC * CC];              // bf16: Wq, Wk, Wo, WvT
__device__ __nv_bfloat16 g_Wov[CC * CC];                  // bf16 composite Wo@Wv
__device__ float         g_bfin[CC];                      // Wo@bv + bo

// ---------------------------------------------------------------------------
// Helpers
// ---------------------------------------------------------------------------
__device__ __forceinline__ float warp_sum(float v) {
    #pragma unroll
    for (int o = 16; o > 0; o >>= 1) v += __shfl_xor_sync(0xffffffffu, v, o);
    return v;
}
__device__ __forceinline__ void ldsm4(uint32_t* r, const void* p) {
    uint32_t a = (uint32_t)__cvta_generic_to_shared(p);
    asm volatile("ldmatrix.sync.aligned.m8n8.x4.shared.b16 {%0,%1,%2,%3}, [%4];"
                 : "=r"(r[0]), "=r"(r[1]), "=r"(r[2]), "=r"(r[3]) : "r"(a));
}
__device__ __forceinline__ void mma16(float* d, const uint32_t* a, const uint32_t* b) {
    asm volatile(
        "mma.sync.aligned.m16n8k16.row.col.f32.bf16.bf16.f32 "
        "{%0,%1,%2,%3}, {%4,%5,%6,%7}, {%8,%9}, {%0,%1,%2,%3};\n"
        : "+f"(d[0]), "+f"(d[1]), "+f"(d[2]), "+f"(d[3])
        : "r"(a[0]), "r"(a[1]), "r"(a[2]), "r"(a[3]), "r"(b[0]), "r"(b[1]));
}
__device__ __forceinline__ uint32_t packbf2(float x, float y) {
    __nv_bfloat162 t = __floats2bfloat162_rn(x, y);
    return *(uint32_t*)&t;
}
__device__ __forceinline__ void cp16(void* smem_dst, const void* gmem_src) {
    uint32_t d = (uint32_t)__cvta_generic_to_shared(smem_dst);
    asm volatile("cp.async.cg.shared.global [%0], [%1], 16;" :: "r"(d), "l"(gmem_src));
}
__device__ __forceinline__ void cp_commit() {
    asm volatile("cp.async.commit_group;" ::: "memory");
}
__device__ __forceinline__ void cp_wait1() {
    asm volatile("cp.async.wait_group 1;" ::: "memory");
}

// ---------------------------------------------------------------------------
// Weight conversion: Wq, Wk, Wo fp32 -> bf16 (slots 0,1,2)
// ---------------------------------------------------------------------------
__global__ __launch_bounds__(256)
void conv_w(const float* __restrict__ Wq, const float* __restrict__ Wk,
            const float* __restrict__ Wo, __nv_bfloat16* __restrict__ dst) {
    const int idx = blockIdx.x * 256 + threadIdx.x;       // 0 .. 196607
    const int mat = idx >> 16;                            // 0..2
    const int off = (idx & 65535) * 4;
    const float* src = (mat == 0) ? Wq : (mat == 1) ? Wk : Wo;
    float4 f = *(const float4*)(src + off);
    uint2 o;
    o.x = packbf2(f.x, f.y);
    o.y = packbf2(f.z, f.w);
    *(uint2*)(dst + (size_t)mat * CC * CC + off) = o;
}

// ---------------------------------------------------------------------------
// Wv transpose: WvT[cin][cout] = bf16(Wv[cout][cin])  (slot 3)
// grid (16,16), block (32,8)
// ---------------------------------------------------------------------------
__global__ __launch_bounds__(256)
void wv_t(const float* __restrict__ Wv, __nv_bfloat16* __restrict__ WvT) {
    __shared__ float t[32][33];
    const int bx = blockIdx.x * 32, by = blockIdx.y * 32;
    const int x = threadIdx.x, y = threadIdx.y;
    #pragma unroll
    for (int i = 0; i < 4; i++)
        t[y + i * 8][x] = Wv[(size_t)(by + y + i * 8) * CC + bx + x];
    __syncthreads();
    #pragma unroll
    for (int i = 0; i < 4; i++)
        WvT[(size_t)(bx + y + i * 8) * CC + by + x] =
            __float2bfloat16_rn(t[x][y + i * 8]);
}

// ---------------------------------------------------------------------------
// bfin[o] = sum_c Wo[o,c] * bv[c] + bo[o]   (2 blocks x 256)
// ---------------------------------------------------------------------------
__global__ __launch_bounds__(256)
void bfin_k(const float* __restrict__ Wo, const float* __restrict__ bv,
            const float* __restrict__ bo, float* __restrict__ bfin) {
    const int o = blockIdx.x * 256 + threadIdx.x;
    float s = bo[o];
    const float* w = Wo + (size_t)o * CC;
    #pragma unroll 8
    for (int c = 0; c < CC; c++) s += w[c] * bv[c];
    bfin[o] = s;
}

// ---------------------------------------------------------------------------
// GroupNorm pass 1 (stats)
// ---------------------------------------------------------------------------
__global__ void gn_stats(const float* __restrict__ x, float2* __restrict__ stats) {
    const int bg = blockIdx.x;
    const int b  = bg / NGROUPS;
    const int g  = bg % NGROUPS;
    const size_t base = ((size_t)b * CC + (size_t)g * CPG) * LL;
    const float* xp = x + base;

    float s = 0.f, s2 = 0.f;
    for (int i = threadIdx.x; i < GROUP_ELEMS / 4; i += blockDim.x) {
        float4 v = ((const float4*)xp)[i];
        s  += (v.x + v.y) + (v.z + v.w);
        s2 += (v.x * v.x + v.y * v.y) + (v.z * v.z + v.w * v.w);
    }
    __shared__ float red1[16], red2[16];
    s = warp_sum(s); s2 = warp_sum(s2);
    const int lane = threadIdx.x & 31, wid = threadIdx.x >> 5;
    if (lane == 0) { red1[wid] = s; red2[wid] = s2; }
    __syncthreads();
    if (threadIdx.x == 0) {
        float t = 0.f, t2 = 0.f;
        #pragma unroll
        for (int i = 0; i < 16; i++) { t += red1[i]; t2 += red2[i]; }
        float mean = t * (1.0f / GROUP_ELEMS);
        float var  = t2 * (1.0f / GROUP_ELEMS) - mean * mean;
        stats[bg] = make_float2(mean, rsqrtf(var + EPS));
    }
}

// ---------------------------------------------------------------------------
// GroupNorm pass 2: normalize + transpose + bf16 -> hT[b][l][c]
// ---------------------------------------------------------------------------
__global__ void gn_norm_t(const float* __restrict__ x,
                          const float2* __restrict__ stats,
                          const float* __restrict__ gamma,
                          const float* __restrict__ beta,
                          __nv_bfloat16* __restrict__ hT) {
    const int b = blockIdx.z;
    const int l0 = blockIdx.x * 32;
    const int c0 = blockIdx.y * 64;
    const int tx = threadIdx.x & 31, ty = threadIdx.x >> 5;
    __shared__ float tile[64][33];

    const float* xb = x + (size_t)b * CC * LL;
    #pragma unroll
    for (int i = 0; i < 8; i++) {
        int c = c0 + i * 8 + ty;
        float2 st = stats[b * NGROUPS + (c >> 4)];
        float gm = gamma[c], bt = beta[c];
        float xv = xb[(size_t)c * LL + l0 + tx];
        tile[c - c0][tx] = (xv - st.x) * st.y * gm + bt;
    }
    __syncthreads();
    __nv_bfloat16* ht = hT + (size_t)b * LL * CC;
    #pragma unroll
    for (int i = 0; i < 4; i++) {
        int l = i * 8 + ty;
        __nv_bfloat162 o;
        o.x = __float2bfloat16_rn(tile[tx * 2][l]);
        o.y = __float2bfloat16_rn(tile[tx * 2 + 1][l]);
        *(__nv_bfloat162*)(ht + (size_t)(l0 + l) * CC + c0 + tx * 2) = o;
    }
}

// ---------------------------------------------------------------------------
// R15 engine: 4 warps (2x2), CTA tile 128x128 x BK=64, warp tile 64x64,
// 2-stage cp.async, 2 CTAs/SM.
//   out[m,n] = sum_k A[m,k] * B[n,k]  (+ epilogue)
// EPI: 0 plain ; 3 exp(v*scale) + rowsum partials ; 4 +bias[n]
//      6 v*invrs[n] + bias[m] + X[m,n], fp32 out   (fused attn output)
// ---------------------------------------------------------------------------
#define BKK 64
#define SROW 72        // 64 + 8 pad (144B rows: 16B aligned, ldmatrix conflict-free)
#define STG_ELEM (128 * SROW)
#define SM_TOTAL (4 * STG_ELEM * 2)   // 2 stages x (A+B) bf16 = 73728 B

template<int EPI, bool OUT_BF16>
__device__ __forceinline__
void gemm_body(__nv_bfloat16* smem, int bx, int by, int z,
               const __nv_bfloat16* __restrict__ Ag, int lda, size_t strA,
               const __nv_bfloat16* __restrict__ Bg, int ldb, size_t strB,
               void* __restrict__ Og, int ldo, size_t strO,
               int K, const float* __restrict__ bias,
               const float* __restrict__ X, size_t strX,
               float scale, float* __restrict__ aux) {
    __nv_bfloat16* smA = smem;                 // 2 stages
    __nv_bfloat16* smB = smem + 2 * STG_ELEM;  // 2 stages

    const int tid = threadIdx.x, lane = tid & 31, warp = tid >> 5;   // warp 0..3
    const int wm = warp >> 1, wn = warp & 1;                          // 2x2
    const int g = lane >> 2, tig = lane & 3;
    const int mBase = by * 128, nBase = bx * 128;

    const int nk = K / BKK;

    auto issue_stage = [&](int kt) {
        if (kt < nk) {
            const int buf = kt & 1;
            const int k0 = kt * BKK;
            __nv_bfloat16* sA = smA + buf * STG_ELEM;
            __nv_bfloat16* sB = smB + buf * STG_ELEM;
            #pragma unroll
            for (int it = 0; it < 8; it++) {
                const int s = tid + it * 128;
                const int row = s >> 3;
                const int col8 = (s & 7) * 8;
                cp16(sA + row * SROW + col8,
                     Ag + strA * z + (size_t)(mBase + row) * lda + k0 + col8);
                cp16(sB + row * SROW + col8,
                     Bg + strB * z + (size_t)(nBase + row) * ldb + k0 + col8);
            }
        }
        cp_commit();
    };

    float acc[4][8][4];
    #pragma unroll
    for (int i = 0; i < 4; i++)
        #pragma unroll
        for (int j = 0; j < 8; j++)
            #pragma unroll
            for (int r = 0; r < 4; r++) acc[i][j][r] = 0.f;

    issue_stage(0);
    issue_stage(1);

    for (int kt = 0; kt < nk; kt++) {
        const int buf = kt & 1;
        const __nv_bfloat16* sA = smA + buf * STG_ELEM;
        const __nv_bfloat16* sB = smB + buf * STG_ELEM;

        cp_wait1();            // stage kt resident
        __syncthreads();

        #pragma unroll
        for (int ks = 0; ks < 4; ks++) {
            uint32_t af[4][4], bf[8][2];
            #pragma unroll
            for (int mt = 0; mt < 4; mt++) {
                const __nv_bfloat16* p = &sA[(wm * 64 + mt * 16 + (lane & 15)) * SROW
                                             + ks * 16 + ((lane >> 4) << 3)];
                ldsm4(af[mt], p);
            }
            #pragma unroll
            for (int np = 0; np < 4; np++) {
                const __nv_bfloat16* p = &sB[(wn * 64 + np * 16 + (lane & 7) + ((lane >> 4) << 3)) * SROW
                                             + ks * 16 + (((lane >> 3) & 1) << 3)];
                uint32_t t[4];
                ldsm4(t, p);
                bf[np * 2][0] = t[0]; bf[np * 2][1] = t[1];
                bf[np * 2 + 1][0] = t[2]; bf[np * 2 + 1][1] = t[3];
            }
            #pragma unroll
            for (int mt = 0; mt < 4; mt++)
                #pragma unroll
                for (int nt = 0; nt < 8; nt++)
                    mma16(acc[mt][nt], af[mt], bf[nt]);
        }

        __syncthreads();       // all warps finished reading buf
        issue_stage(kt + 2);   // refill it
    }

    // ---- epilogue ----
    float bn0[8], bn1[8];
    if (EPI == 4) {
        #pragma unroll
        for (int nt = 0; nt < 8; nt++) {
            int col = nBase + wn * 64 + nt * 8 + tig * 2;
            bn0[nt] = bias[col]; bn1[nt] = bias[col + 1];
        }
    }
    if (EPI == 6) {            // per-column 1/rowsum
        #pragma unroll
        for (int nt = 0; nt < 8; nt++) {
            int col = nBase + wn * 64 + nt * 8 + tig * 2;
            bn0[nt] = aux[(size_t)z * LL + col];
            bn1[nt] = aux[(size_t)z * LL + col + 1];
        }
    }
    #pragma unroll
    for (int mt = 0; mt < 4; mt++) {
        #pragma unroll
        for (int half = 0; half < 2; half++) {
            const int row = mBase + wm * 64 + mt * 16 + g + half * 8;
            float bm = (EPI == 6) ? bias[row] : 0.f;
            float rsum = 0.f;
            #pragma unroll
            for (int nt = 0; nt < 8; nt++) {
                const int col = nBase + wn * 64 + nt * 8 + tig * 2;
                float v0 = acc[mt][nt][half * 2 + 0];
                float v1 = acc[mt][nt][half * 2 + 1];
                if (EPI == 4) { v0 += bn0[nt]; v1 += bn1[nt]; }
                if (EPI == 6) {
                    const float* xr = X + strX * z + (size_t)row * ldo + col;
                    v0 = v0 * bn0[nt] + bm + xr[0];
                    v1 = v1 * bn1[nt] + bm + xr[1];
                }
                if (EPI == 3) {
                    v0 = __expf(v0 * scale);
                    v1 = __expf(v1 * scale);
                    __nv_bfloat162 st = __floats2bfloat162_rn(v0, v1);
                    *(__nv_bfloat162*)((__nv_bfloat16*)Og + strO * z
                                       + (size_t)row * ldo + col) = st;
                    rsum += __bfloat162float(st.x) + __bfloat162float(st.y);
                } else if constexpr (OUT_BF16) {
                    __nv_bfloat162 st = __floats2bfloat162_rn(v0, v1);
                    *(__nv_bfloat162*)((__nv_bfloat16*)Og + strO * z
                                       + (size_t)row * ldo + col) = st;
                } else {
                    float2 st = { v0, v1 };
                    *(float2*)((float*)Og + strO * z + (size_t)row * ldo + col) = st;
                }
            }
            if (EPI == 3) {
                rsum += __shfl_xor_sync(0xffffffffu, rsum, 1);
                rsum += __shfl_xor_sync(0xffffffffu, rsum, 2);
                if (tig == 0)
                    aux[((size_t)z * LL + row) * 32 + bx * 2 + wn] = rsum;
            }
        }
    }
}

// ---------------------------------------------------------------------------
// Kernel wrappers
// ---------------------------------------------------------------------------
template<int EPI, bool OUT_BF16>
__global__ __launch_bounds__(128, 2)
void gemm_k(const __nv_bfloat16* __restrict__ Ag, int lda, size_t strA,
            const __nv_bfloat16* __restrict__ Bg, int ldb, size_t strB,
            void* __restrict__ Og, int ldo, size_t strO,
            int K, const float* __restrict__ bias,
            const float* __restrict__ X, size_t strX,
            float scale, float* __restrict__ aux) {
    extern __shared__ __align__(16) __nv_bfloat16 smem[];
    gemm_body<EPI, OUT_BF16>(
        smem, blockIdx.x, blockIdx.y, blockIdx.z,
        Ag, lda, strA, Bg, ldb, strB, Og, ldo, strO,
        K, bias, X, strX, scale, aux);
}

// Merged q/k/V projections in one 1D launch.
//  blocks [0, 1024):  qk — bx=bid&3, by=(bid>>2)&15, zz=bid>>6 (0..15)
//  blocks [1024, 1536): V — t=bid-1024: bx=t&15, by=(t>>4)&3, z=t>>6
#define QK_BLOCKS 1024
#define QKV_BLOCKS 1536

__global__ __launch_bounds__(128, 2)
void qkv_k(const __nv_bfloat16* __restrict__ hT,
           const __nv_bfloat16* __restrict__ Wbf,
           const __nv_bfloat16* __restrict__ Wov,
           const float* __restrict__ bq, __nv_bfloat16* __restrict__ qT,
           const float* __restrict__ bk, __nv_bfloat16* __restrict__ kT,
           __nv_bfloat16* __restrict__ v) {
    extern __shared__ __align__(16) __nv_bfloat16 smem[];
    const size_t CL = (size_t)CC * LL;
    const size_t WSZ = (size_t)CC * CC;
    const int bid = blockIdx.x;
    if (bid < QK_BLOCKS) {
        const int bx = bid & 3;
        const int by = (bid >> 2) & 15;
        const int zz = bid >> 6;
        const __nv_bfloat16* W = (zz < 8) ? Wbf : Wbf + WSZ;
        const float* b = (zz < 8) ? bq : bk;
        __nv_bfloat16* O = (zz < 8) ? qT : kT;
        const int z = (zz < 8) ? zz : zz - 8;
        // qT/kT[l][o] = hT @ W^T + b[n]   (M=L, N=C, K=C)
        gemm_body<4, true>(
            smem, bx, by, z,
            hT, CC, CL, W, CC, 0, O, CC, CL, CC, b, nullptr, 0, 0.f, nullptr);
    } else {
        const int t = bid - QK_BLOCKS;
        const int bx = t & 15;
        const int by = (t >> 4) & 3;
        const int z = t >> 6;
        // v''[c][l] = Wov @ h  (bias folded into bfin)   (M=C, N=L, K=C)
        gemm_body<0, true>(
            smem, bx, by, z,
            Wov, CC, 0, hT, CC, CL, v, LL, CL, CC, nullptr,
            nullptr, 0, 0.f, nullptr);
    }
}

// ---------------------------------------------------------------------------
// Rowsum reduce: 32 partials per row -> 1/rowsum.  grid B*LL/8, 256 thr.
// ---------------------------------------------------------------------------
__global__ __launch_bounds__(256)
void rs_reduce(const float* __restrict__ part, float* __restrict__ invrs) {
    const int row = blockIdx.x * 8 + (threadIdx.x >> 5);
    const int lane = threadIdx.x & 31;
    float s = part[(size_t)row * 32 + lane];
    s = warp_sum(s);
    if (lane == 0) invrs[row] = 1.0f / s;
}

// ---------------------------------------------------------------------------
// Launch
// ---------------------------------------------------------------------------
extern "C" void kernel_launch(void* const* d_in, const int* in_sizes, int n_in,
                              void* d_out, int out_size) {
    const float* x        = (const float*)d_in[0];
    const float* gn_gamma = (const float*)d_in[1];
    const float* gn_beta  = (const float*)d_in[2];
    const float* Wq = (const float*)d_in[3];
    const float* bq = (const float*)d_in[4];
    const float* Wk = (const float*)d_in[5];
    const float* bk = (const float*)d_in[6];
    const float* Wv = (const float*)d_in[7];
    const float* bv = (const float*)d_in[8];
    const float* Wo = (const float*)d_in[9];
    const float* bo = (const float*)d_in[10];
    float* out = (float*)d_out;

    __nv_bfloat16 *hT, *qT, *kT, *v, *e, *Wbf, *Wov;
    float *part, *invrs, *bfin; float2* stats;
    cudaGetSymbolAddress((void**)&hT, g_hT);
    cudaGetSymbolAddress((void**)&qT, g_qT);
    cudaGetSymbolAddress((void**)&kT, g_kT);
    cudaGetSymbolAddress((void**)&v,  g_v);
    cudaGetSymbolAddress((void**)&e,  g_e);
    cudaGetSymbolAddress((void**)&part, g_part);
    cudaGetSymbolAddress((void**)&invrs, g_invrs);
    cudaGetSymbolAddress((void**)&stats, g_stats);
    cudaGetSymbolAddress((void**)&Wbf, g_Wbf);
    cudaGetSymbolAddress((void**)&Wov, g_Wov);
    cudaGetSymbolAddress((void**)&bfin, g_bfin);

    const size_t CL  = (size_t)CC * LL;
    const size_t LLs = (size_t)LL * LL;
    const size_t WSZ = (size_t)CC * CC;
    const float scale = 0.044194173824159216f;   // 1/sqrt(512)

    cudaFuncSetAttribute(qkv_k,
                         cudaFuncAttributeMaxDynamicSharedMemorySize, SM_TOTAL);
    cudaFuncSetAttribute(gemm_k<0, true>,
                         cudaFuncAttributeMaxDynamicSharedMemorySize, SM_TOTAL);
    cudaFuncSetAttribute(gemm_k<3, true>,
                         cudaFuncAttributeMaxDynamicSharedMemorySize, SM_TOTAL);
    cudaFuncSetAttribute(gemm_k<6, false>,
                         cudaFuncAttributeMaxDynamicSharedMemorySize, SM_TOTAL);

    // 0. weight prep: bf16 conversions, Wv transpose, composite Wov, bfin
    conv_w<<<768, 256>>>(Wq, Wk, Wo, Wbf);
    wv_t<<<dim3(16, 16), dim3(32, 8)>>>(Wv, Wbf + 3 * WSZ);
    bfin_k<<<2, 256>>>(Wo, bv, bo, bfin);
    // Wov[o][cin] = sum_cout Wo[o,cout] * WvT[cin,cout]   (M=N=K=512)
    gemm_k<0, true><<<dim3(4, 4, 1), 128, SM_TOTAL>>>(
        Wbf + 2 * WSZ, CC, 0, Wbf + 3 * WSZ, CC, 0, Wov, CC, 0,
        CC, nullptr, nullptr, 0, 0.f, nullptr);

    // 1. GroupNorm
    gn_stats<<<BATCH * NGROUPS, 512>>>(x, stats);
    gn_norm_t<<<dim3(LL / 32, CC / 64, BATCH), 256>>>(x, stats, gn_gamma, gn_beta, hT);

    // 2. merged q/k/V'' projections (one 1D launch, 1536 blocks)
    qkv_k<<<QKV_BLOCKS, 128, SM_TOTAL>>>(hT, Wbf, Wov, bq, qT, bk, kT, v);

    // 3. e[i][j] = exp(scale * qT@kT^T), + rowsum partials  (M=N=L, K=C)
    dim3 gS(LL / 128, LL / 128, BATCH);
    gemm_k<3, true><<<gS, 128, SM_TOTAL>>>(
        qT, CC, CL, kT, CC, CL, e, LL, LLs, CC, nullptr, nullptr, 0, scale, part);

    // 4. invrs[i] = 1 / rowsum(i)
    rs_reduce<<<BATCH * LL / 8, 256>>>(part, invrs);

    // 5. out[o][i] = x + (v'' @ e^T)[o,i] * invrs[i] + bfin[o]
    //    (M=C rows=o, N=L cols=i, K=L)  — Wo GEMM folded away
    dim3 gF(LL / 128, CC / 128, BATCH);
    gemm_k<6, false><<<gF, 128, SM_TOTAL>>>(
        v, LL, CL, e, LL, LLs, out, LL, CL, LL, bfin, x, CL, 0.f, invrs);
}